// round 6
// baseline (speedup 1.0000x reference)
#include <cuda_runtime.h>

#define NT 512
#define L_IN 4096
#define DZV 30
#define CV 10
#define NPG 15
#define B_TOT 512

typedef unsigned long long u64;

// head weights stay in constant (tiny)
__constant__ float cWh[DZV*80];   // [d][c][j]
__constant__ float cZ[DZV];

// duplicated-weight blocks, one 408-u64 block per net:
// [0..96)   W1d: ch*12 + k*4 + oc   (oc<4)
// [96..192) W2d: ch*24 + k*8 + oc   (oc<8, ch<4)
// [192..384)W3d: ch*24 + k*8 + oc   (oc<8, ch<8)
// [384..388) b1d, [388..396) b2d, [396..404) b3d, pad to 408
__device__ u64 g_wdup[DZV*408];

__device__ __forceinline__ u64 f2_as_u64(float2 v) {
    union { float2 f; u64 u; } c; c.f = v; return c.u;
}
__device__ __forceinline__ float2 u64_as_f2(u64 v) {
    union { float2 f; u64 u; } c; c.u = v; return c.f;
}
__device__ __forceinline__ u64 pack2(float a, float b) {
    u64 r; asm("mov.b64 %0, {%1, %2};" : "=l"(r) : "f"(a), "f"(b)); return r;
}
__device__ __forceinline__ u64 ffma2(u64 a, u64 b, u64 c) {
    u64 d; asm("fma.rn.f32x2 %0, %1, %2, %3;" : "=l"(d) : "l"(a), "l"(b), "l"(c)); return d;
}

// ---- prep: build dup'd weight blocks + init out with folded head bias ----
__global__ void prep_kernel(const float* __restrict__ W1, const float* __restrict__ b1,
                            const float* __restrict__ W2, const float* __restrict__ b2,
                            const float* __restrict__ W3, const float* __restrict__ b3,
                            const float* __restrict__ z,  const float* __restrict__ bh,
                            float* __restrict__ out) {
    int i = blockIdx.x * blockDim.x + threadIdx.x;
    if (i < DZV*404) {
        int n = i / 404, r = i % 404;
        float v;
        if (r < 96) {
            int ch = r / 12, k = (r % 12) / 4, oc = r & 3;
            v = W1[n*96 + oc*24 + ch*3 + k];
        } else if (r < 192) {
            int t = r - 96, ch = t / 24, k = (t % 24) / 8, oc = t & 7;
            v = W2[n*96 + oc*12 + ch*3 + k];
        } else if (r < 384) {
            int t = r - 192, ch = t / 24, k = (t % 24) / 8, oc = t & 7;
            v = W3[n*192 + oc*24 + ch*3 + k];
        } else if (r < 388) v = b1[n*4 + (r-384)];
        else if (r < 396)   v = b2[n*8 + (r-388)];
        else                v = b3[n*8 + (r-396)];
        g_wdup[n*408 + r] = pack2(v, v);
    }
    if (i < B_TOT*CV) {
        int c = i % CV;
        float s = 0.f;
        #pragma unroll
        for (int d = 0; d < DZV; d++) s = fmaf(z[d], bh[d*CV + c], s);
        out[i] = s;
    }
}

// ---- smem float offsets ----
#define XE_BASE 0          // [8][2056]  x[2i]
#define XO_BASE 16452      // [8][2056]  x[2i+1]  (+4 stagger)
#define HE_BASE 32904      // [4][1032]  h1[2j]
#define HO_BASE 37036      // [4][1032]  h1[2j+1]
#define H2_BASE 41168      // [8][1032]  h2 (interleaved)
#define WSM_OFF 49424      // 408 u64 = 816 floats (16B aligned: 49424*4 % 16 == 0)
#define RED_OFF 50240      // [16][8]
#define SMEM_FLOATS 50368  // 201472 B

__global__ __launch_bounds__(NT, 1)
void ensemble_kernel(const int* __restrict__ ids,
                     const float* __restrict__ mask,
                     const float* __restrict__ embed,
                     float* __restrict__ out)
{
    extern __shared__ float sm[];
    ulonglong2* wsm2 = (ulonglong2*)(sm + WSM_OFF);
    float* red = sm + RED_OFF;

    const int tid  = threadIdx.x;
    const int lane = tid & 31;
    const int warp = tid >> 5;
    const int b    = blockIdx.x;
    const int g    = blockIdx.y;

    // zero padding slots (read by dead/pad positions only)
    if (tid < 8)  sm[XE_BASE + tid*2056 + 2048] = 0.f;              // XE[ch][2048]
    if (tid >= 8 && tid < 12) sm[HE_BASE + (tid-8)*1032 + 1024] = 0.f;  // HE[ch][1024]
    if (tid >= 16 && tid < 32) {
        int ch = (tid - 16) >> 1;
        sm[H2_BASE + ch*1032 + 1024 + (tid & 1)] = 0.f;             // h2[ch][1024..1025]
    }

    // ---- gather masked embeddings, channel-major, even/odd deinterleaved ----
    #pragma unroll 1
    for (int i = tid; i < L_IN; i += NT) {
        int   id = __ldg(&ids[b*L_IN + i]);
        float m  = __ldg(&mask[b*L_IN + i]);
        float4 e0 = __ldg((const float4*)(embed + (size_t)id*8));
        float4 e1 = __ldg((const float4*)(embed + (size_t)id*8 + 4));
        int base = ((i & 1) ? XO_BASE : XE_BASE) + (i >> 1);
        sm[base + 0*2056] = e0.x*m; sm[base + 1*2056] = e0.y*m;
        sm[base + 2*2056] = e0.z*m; sm[base + 3*2056] = e0.w*m;
        sm[base + 4*2056] = e1.x*m; sm[base + 5*2056] = e1.y*m;
        sm[base + 6*2056] = e1.z*m; sm[base + 7*2056] = e1.w*m;
    }
    __syncthreads();

    float oacc = 0.f;   // warp0, lane<CV

    #pragma unroll 1
    for (int dn = 0; dn < NPG; dn++) {
        const int d = g*NPG + dn;

        // ---- stage this net's dup'd weights into smem (3.2 KB) ----
        if (tid < 202)
            ((float4*)(sm + WSM_OFF))[tid] =
                __ldg((const float4*)(g_wdup + (size_t)d*408) + tid);
        __syncthreads();

        // ======== conv1: x(even/odd) -> h1(even/odd), K3 S2, 8->4, ReLU ========
        // pos-pair (2m, 2m+1); m = s*512 + tid, s<2
        {
            u64 acc[2][4];
            {
                const ulonglong2 b0 = wsm2[192], b1 = wsm2[193];
                #pragma unroll
                for (int s = 0; s < 2; s++) {
                    acc[s][0] = b0.x; acc[s][1] = b0.y;
                    acc[s][2] = b1.x; acc[s][3] = b1.y;
                }
            }
            #pragma unroll
            for (int ch = 0; ch < 8; ch++) {
                const ulonglong2 w00 = wsm2[ch*6+0], w01 = wsm2[ch*6+1];
                const ulonglong2 w10 = wsm2[ch*6+2], w11 = wsm2[ch*6+3];
                const ulonglong2 w20 = wsm2[ch*6+4], w21 = wsm2[ch*6+5];
                const float* XEr = sm + XE_BASE + ch*2056;
                const float* XOr = sm + XO_BASE + ch*2056;
                #pragma unroll
                for (int s = 0; s < 2; s++) {
                    const int m = s*NT + tid;
                    float2 ef = *(const float2*)(XEr + 2*m);   // (x[4m],   x[4m+2])
                    float2 of = *(const float2*)(XOr + 2*m);   // (x[4m+1], x[4m+3])
                    float  e2 = XEr[2*m + 2];                  //  x[4m+4]
                    const u64 pe = f2_as_u64(ef);
                    const u64 po = f2_as_u64(of);
                    const u64 pc = pack2(ef.y, e2);
                    acc[s][0]=ffma2(w00.x,pe,acc[s][0]); acc[s][1]=ffma2(w00.y,pe,acc[s][1]);
                    acc[s][2]=ffma2(w01.x,pe,acc[s][2]); acc[s][3]=ffma2(w01.y,pe,acc[s][3]);
                    acc[s][0]=ffma2(w10.x,po,acc[s][0]); acc[s][1]=ffma2(w10.y,po,acc[s][1]);
                    acc[s][2]=ffma2(w11.x,po,acc[s][2]); acc[s][3]=ffma2(w11.y,po,acc[s][3]);
                    acc[s][0]=ffma2(w20.x,pc,acc[s][0]); acc[s][1]=ffma2(w20.y,pc,acc[s][1]);
                    acc[s][2]=ffma2(w21.x,pc,acc[s][2]); acc[s][3]=ffma2(w21.y,pc,acc[s][3]);
                }
            }
            #pragma unroll
            for (int s = 0; s < 2; s++) {
                const int m = s*NT + tid;
                #pragma unroll
                for (int oc = 0; oc < 4; oc++) {
                    float2 v = u64_as_f2(acc[s][oc]);
                    sm[HE_BASE + oc*1032 + m] = fmaxf(v.x, 0.f);
                    sm[HO_BASE + oc*1032 + m] = fmaxf(v.y, 0.f);
                }
            }
        }
        __syncthreads();

        // ======== conv2: h1(even/odd) -> h2, K3 S2, 4->8, ReLU ========
        // pos-pair (2*tid, 2*tid+1)
        {
            u64 acc[8];
            {
                const ulonglong2 b0 = wsm2[194], b1 = wsm2[195];
                const ulonglong2 b2 = wsm2[196], b3 = wsm2[197];
                acc[0]=b0.x; acc[1]=b0.y; acc[2]=b1.x; acc[3]=b1.y;
                acc[4]=b2.x; acc[5]=b2.y; acc[6]=b3.x; acc[7]=b3.y;
            }
            const int m = tid;
            #pragma unroll
            for (int ch = 0; ch < 4; ch++) {
                const ulonglong2* wv = wsm2 + 48 + ch*12;   // [k<3][ocpair<4]
                const float* HEr = sm + HE_BASE + ch*1032;
                const float* HOr = sm + HO_BASE + ch*1032;
                float2 ef = *(const float2*)(HEr + 2*m);
                float2 of = *(const float2*)(HOr + 2*m);
                float  e2 = HEr[2*m + 2];
                const u64 pe = f2_as_u64(ef);
                const u64 po = f2_as_u64(of);
                const u64 pc = pack2(ef.y, e2);
                #pragma unroll
                for (int j = 0; j < 4; j++) {
                    const ulonglong2 wk0 = wv[0*4 + j];
                    const ulonglong2 wk1 = wv[1*4 + j];
                    const ulonglong2 wk2 = wv[2*4 + j];
                    acc[2*j+0] = ffma2(wk0.x, pe, acc[2*j+0]);
                    acc[2*j+1] = ffma2(wk0.y, pe, acc[2*j+1]);
                    acc[2*j+0] = ffma2(wk1.x, po, acc[2*j+0]);
                    acc[2*j+1] = ffma2(wk1.y, po, acc[2*j+1]);
                    acc[2*j+0] = ffma2(wk2.x, pc, acc[2*j+0]);
                    acc[2*j+1] = ffma2(wk2.y, pc, acc[2*j+1]);
                }
            }
            #pragma unroll
            for (int oc = 0; oc < 8; oc++) {
                float2 v = u64_as_f2(acc[oc]);
                float2 st = make_float2(fmaxf(v.x, 0.f), fmaxf(v.y, 0.f));
                *(float2*)(sm + H2_BASE + oc*1032 + 2*m) = st;
            }
        }
        __syncthreads();

        // ======== conv3 + ReLU + pool: h2 -> psum[8], K3 S1 ========
        // pos-pair (2*tid, 2*tid+1); valid output pos < 1021
        float psum[8];
        #pragma unroll
        for (int i = 0; i < 8; i++) psum[i] = 0.f;
        {
            u64 acc[8];
            {
                const ulonglong2 b0 = wsm2[198], b1 = wsm2[199];
                const ulonglong2 b2 = wsm2[200], b3 = wsm2[201];
                acc[0]=b0.x; acc[1]=b0.y; acc[2]=b1.x; acc[3]=b1.y;
                acc[4]=b2.x; acc[5]=b2.y; acc[6]=b3.x; acc[7]=b3.y;
            }
            const int p = 2*tid;
            #pragma unroll
            for (int ch = 0; ch < 8; ch++) {
                const ulonglong2* wv = wsm2 + 96 + ch*12;
                const float* H2r = sm + H2_BASE + ch*1032;
                float2 a  = *(const float2*)(H2r + p);       // (h2[p],   h2[p+1])
                float2 bq = *(const float2*)(H2r + p + 2);   // (h2[p+2], h2[p+3])
                const u64 k0 = f2_as_u64(a);
                const u64 k2 = f2_as_u64(bq);
                const u64 k1 = pack2(a.y, bq.x);
                #pragma unroll
                for (int j = 0; j < 4; j++) {
                    const ulonglong2 wk0 = wv[0*4 + j];
                    const ulonglong2 wk1 = wv[1*4 + j];
                    const ulonglong2 wk2 = wv[2*4 + j];
                    acc[2*j+0] = ffma2(wk0.x, k0, acc[2*j+0]);
                    acc[2*j+1] = ffma2(wk0.y, k0, acc[2*j+1]);
                    acc[2*j+0] = ffma2(wk1.x, k1, acc[2*j+0]);
                    acc[2*j+1] = ffma2(wk1.y, k1, acc[2*j+1]);
                    acc[2*j+0] = ffma2(wk2.x, k2, acc[2*j+0]);
                    acc[2*j+1] = ffma2(wk2.y, k2, acc[2*j+1]);
                }
            }
            const bool vlo = (2*tid     < 1021);
            const bool vhi = (2*tid + 1 < 1021);
            #pragma unroll
            for (int oc = 0; oc < 8; oc++) {
                float2 v = u64_as_f2(acc[oc]);
                psum[oc] += vlo ? fmaxf(v.x, 0.f) : 0.f;
                psum[oc] += vhi ? fmaxf(v.y, 0.f) : 0.f;
            }
        }

        // ---- warp reduce psum -> red[warp][oc] ----
        #pragma unroll
        for (int oc = 0; oc < 8; oc++) {
            float s = psum[oc];
            #pragma unroll
            for (int off = 16; off > 0; off >>= 1)
                s += __shfl_down_sync(0xFFFFFFFFu, s, off);
            if (lane == 0) red[warp*8 + oc] = s;
        }
        __syncthreads();

        // ---- warp0: cross-warp reduce (16 warps) + head matvec ----
        if (warp == 0) {
            float s = red[lane] + red[lane+32] + red[lane+64] + red[lane+96];
            s += __shfl_xor_sync(0xFFFFFFFFu, s, 8);
            s += __shfl_xor_sync(0xFFFFFFFFu, s, 16);
            float pj[8];
            #pragma unroll
            for (int j = 0; j < 8; j++)
                pj[j] = __shfl_sync(0xFFFFFFFFu, s, j);
            if (lane < CV) {
                float v = 0.f;
                #pragma unroll
                for (int j = 0; j < 8; j++)
                    v = fmaf(pj[j], cWh[(d*CV + lane)*8 + j], v);
                oacc = fmaf(v, cZ[d] * (1.0f/1021.0f), oacc);
            }
        }
        // red hazard: next red-write only after 3 more barriers warp0 also passes.
    }

    if (warp == 0 && lane < CV)
        atomicAdd(&out[b*CV + lane], oacc);
}

extern "C" void kernel_launch(void* const* d_in, const int* in_sizes, int n_in,
                              void* d_out, int out_size) {
    const int*   ids  = (const int*)  d_in[0];
    const float* mask = (const float*)d_in[1];
    const float* z    = (const float*)d_in[2];
    const float* emb  = (const float*)d_in[3];
    const float* W1   = (const float*)d_in[4];
    const float* b1   = (const float*)d_in[5];
    const float* W2   = (const float*)d_in[6];
    const float* b2   = (const float*)d_in[7];
    const float* W3   = (const float*)d_in[8];
    const float* b3   = (const float*)d_in[9];
    const float* Wh   = (const float*)d_in[10];
    const float* bh   = (const float*)d_in[11];
    float* out = (float*)d_out;

    cudaMemcpyToSymbolAsync(cWh, Wh, DZV*80*sizeof(float), 0, cudaMemcpyDeviceToDevice, 0);
    cudaMemcpyToSymbolAsync(cZ,  z,  DZV*sizeof(float),    0, cudaMemcpyDeviceToDevice, 0);

    prep_kernel<<<(DZV*404 + 255)/256, 256>>>(W1, b1, W2, b2, W3, b3, z, bh, out);

    cudaFuncSetAttribute(ensemble_kernel,
                         cudaFuncAttributeMaxDynamicSharedMemorySize,
                         SMEM_FLOATS * (int)sizeof(float));
    ensemble_kernel<<<dim3(B_TOT, 2), NT, SMEM_FLOATS * (int)sizeof(float)>>>(ids, mask, emb, out);
}